// round 12
// baseline (speedup 1.0000x reference)
#include <cuda_runtime.h>
#include <cstdint>

// Conv_39333310497378 — fp16 mma.sync; prep kernels convert x,W to fp16 once;
// main: 256 thr (m2 x n2 x h2 warps), double-buffered x, 3 CTAs/SM.
// pot(b,s,o) = max_{h<4} sum_{k<240} x[b*1640 + 160s + 40h + k] * W[s,o,k]
// out: pots [B,50,9] then spikes [B,50,9] (f32), index b*450 + o*9 + s.

#define NB      16384
#define XSLAB   1640
#define THRESH  6.2f
#define NTHR    256

#define XSTRW   180        // xbuf row stride (words); banks 20*lr+lc: full perm
#define WSTRW   124        // wbuf row stride (words); banks 28*lr+lc: full perm
#define WROWS   56
#define WSEC    (WROWS * WSTRW)              // 6944 words

__device__ uint32_t g_w16[9 * WSEC];         // 250 KB (zero-init pad rows 50..55)
__device__ uint32_t g_x16[(size_t)NB * 820]; // 53.7 MB fp16 slab copy of x

// smem words: xbuf0 [0,5760) | xbuf1 [5760,11520) | wbuf [11520,18464)
#define XBUF_WORDS (32 * XSTRW)              // 5760
#define WB_OFF     (2 * XBUF_WORDS)
#define SMEM_BYTES ((WB_OFF + WSEC) * 4)     // 73856 -> 3 CTAs/SM

// ---------------- prep kernels ----------------
__global__ void prep_x_kernel(const float* __restrict__ x)
{
  int i = blockIdx.x * blockDim.x + threadIdx.x;   // float4 chunks
  if (i >= NB * 410) return;
  int b = i / 410, q = i - b * 410;
  float4 v = *reinterpret_cast<const float4*>(x + (size_t)b * XSLAB + 4 * q);
  uint32_t w0, w1;
  asm("cvt.rn.f16x2.f32 %0, %1, %2;" : "=r"(w0) : "f"(v.y), "f"(v.x));
  asm("cvt.rn.f16x2.f32 %0, %1, %2;" : "=r"(w1) : "f"(v.w), "f"(v.z));
  *reinterpret_cast<uint2*>(g_x16 + (size_t)b * 820 + 2 * q) = make_uint2(w0, w1);
}

__global__ void prep_w_kernel(const float* __restrict__ W)
{
  int i = blockIdx.x * blockDim.x + threadIdx.x;   // 8-float chunks
  if (i >= 9 * 50 * 30) return;
  int s = i / 1500, rem = i - s * 1500;
  int o = rem / 30,  q  = rem - o * 30;
  const float* src = W + ((size_t)(s * 50 + o) * 240 + 8 * q);
  float4 v0 = *reinterpret_cast<const float4*>(src);
  float4 v1 = *reinterpret_cast<const float4*>(src + 4);
  uint4 t;
  asm("cvt.rn.f16x2.f32 %0, %1, %2;" : "=r"(t.x) : "f"(v0.y), "f"(v0.x));
  asm("cvt.rn.f16x2.f32 %0, %1, %2;" : "=r"(t.y) : "f"(v0.w), "f"(v0.z));
  asm("cvt.rn.f16x2.f32 %0, %1, %2;" : "=r"(t.z) : "f"(v1.y), "f"(v1.x));
  asm("cvt.rn.f16x2.f32 %0, %1, %2;" : "=r"(t.w) : "f"(v1.w), "f"(v1.z));
  *reinterpret_cast<uint4*>(g_w16 + s * WSEC + o * WSTRW + 4 * q) = t;
}

// ---------------- main kernel ----------------
__device__ __forceinline__ uint32_t s2u(const void* p){
  uint32_t a;
  asm("{.reg .u64 t; cvta.to.shared.u64 t, %1; cvt.u32.u64 %0, t;}" : "=r"(a) : "l"(p));
  return a;
}
__device__ __forceinline__ void cp16(uint32_t dst, const void* src){
  asm volatile("cp.async.cg.shared.global [%0], [%1], 16;" :: "r"(dst), "l"(src) : "memory");
}

// Each warp: 2 h-windows (h = 2*wh + hh), JN n-frags. Writes per-element
// partial max into mx[j][c].
template<int JN>
__device__ __forceinline__ void core(const uint32_t* __restrict__ xb,
                                     const uint32_t* __restrict__ wb,
                                     int wm, int wn, int wh, int lr, int lc,
                                     float (&mx)[4][4])
{
  float d[2][JN][4];
  #pragma unroll
  for (int hh = 0; hh < 2; hh++)
    #pragma unroll
    for (int j = 0; j < JN; j++)
      #pragma unroll
      for (int c = 0; c < 4; c++) d[hh][j][c] = 0.f;

  const int ar = (wm * 16 + lr) * XSTRW + lc + 40 * wh;  // +20*(2*wh) words
  const int wr = (wn * 32 + lr) * WSTRW + lc;

  #pragma unroll 5
  for (int ks = 0; ks < 15; ks++)
  {
    const int ko = 8 * ks;
    uint32_t b[JN][2];
    #pragma unroll
    for (int j = 0; j < JN; j++){
      b[j][0] = wb[wr + j * (8 * WSTRW) + ko];
      b[j][1] = wb[wr + j * (8 * WSTRW) + ko + 4];
    }
    uint32_t a[2][4];
    #pragma unroll
    for (int hh = 0; hh < 2; hh++){
      int wa = ar + 20 * hh + ko;
      a[hh][0] = xb[wa];
      a[hh][1] = xb[wa + 8 * XSTRW];
      a[hh][2] = xb[wa + 4];
      a[hh][3] = xb[wa + 8 * XSTRW + 4];
    }
    #pragma unroll
    for (int hh = 0; hh < 2; hh++)
      #pragma unroll
      for (int j = 0; j < JN; j++)
        asm("mma.sync.aligned.m16n8k16.row.col.f32.f16.f16.f32 "
            "{%0,%1,%2,%3},{%4,%5,%6,%7},{%8,%9},{%0,%1,%2,%3};"
            : "+f"(d[0 + hh][j][0]), "+f"(d[0 + hh][j][1]),
              "+f"(d[0 + hh][j][2]), "+f"(d[0 + hh][j][3])
            : "r"(a[hh][0]), "r"(a[hh][1]), "r"(a[hh][2]), "r"(a[hh][3]),
              "r"(b[j][0]), "r"(b[j][1]));
  }

  #pragma unroll
  for (int j = 0; j < JN; j++)
    #pragma unroll
    for (int c = 0; c < 4; c++)
      mx[j][c] = fmaxf(d[0][j][c], d[1][j][c]);
}

__global__ void __launch_bounds__(NTHR, 3)
conv_main(float* __restrict__ out)
{
  extern __shared__ uint32_t sm[];
  uint32_t* xbuf[2] = { sm, sm + XBUF_WORDS };
  uint32_t* wb      = sm + WB_OFF;

  const uint32_t xsa0 = s2u(sm);
  const uint32_t wsa  = s2u(wb);

  const int tid  = threadIdx.x;
  const int warp = tid >> 5, lane = tid & 31;
  const int lr = lane >> 2, lc = lane & 3;
  const int wm = warp & 1, wn = (warp >> 1) & 1, wh = warp >> 2;
  const int b0 = blockIdx.x * 32;
  const int JN = (wn == 0) ? 4 : 3;

  auto load_x = [&](int s, int buf){
    const uint32_t base = xsa0 + (uint32_t)(buf * XBUF_WORDS) * 4u;
    #pragma unroll 2
    for (int i = tid; i < 1440; i += NTHR){      // 45 16B-chunks x 32 rows
      int row = i / 45, c = i - row * 45;
      cp16(base + (uint32_t)(row * XSTRW + 4 * c) * 4u,
           g_x16 + (size_t)(b0 + row) * 820 + 80 * s + 4 * c);
    }
  };
  auto load_w = [&](int s){
    const uint32_t* src = g_w16 + s * WSEC;
    #pragma unroll 2
    for (int i = tid; i < WSEC / 4; i += NTHR)   // 1736 16B chunks
      cp16(wsa + 16u * (uint32_t)i, src + 4 * i);
  };

  load_x(0, 0);
  load_w(0);
  asm volatile("cp.async.commit_group;" ::: "memory");

  int cur = 0;
  for (int s = 0; s < 9; s++)
  {
    if (s < 8){                          // x(s+1) flies over compute(s)
      load_x(s + 1, cur ^ 1);
      asm volatile("cp.async.commit_group;" ::: "memory");
      asm volatile("cp.async.wait_group 1;" ::: "memory");
    } else {
      asm volatile("cp.async.wait_group 0;" ::: "memory");
    }
    __syncthreads();                     // xbuf[cur] + wbuf(s) visible

    float mx[4][4];
    if (wn == 0) core<4>(xbuf[cur], wb, wm, 0, wh, lr, lc, mx);
    else         core<3>(xbuf[cur], wb, wm, 1, wh, lr, lc, mx);

    __syncthreads();                     // xbuf[cur]+wbuf reads complete
    if (s < 8){                          // wbuf free -> prefetch W(s+1)
      load_w(s + 1);
      asm volatile("cp.async.commit_group;" ::: "memory");
    }

    // h-reduction: wh=1 publishes partials into the consumed xbuf[cur]
    float* part = reinterpret_cast<float*>(xbuf[cur]);
    if (wh == 1){
      #pragma unroll
      for (int j = 0; j < 4; j++){
        if (j >= JN) break;
        #pragma unroll
        for (int c = 0; c < 4; c++){
          int o = wn * 32 + 8 * j + 2 * lc + (c & 1);
          if (o < 50){
            int rl = wm * 16 + lr + ((c >> 1) << 3);
            part[rl * 50 + o] = mx[j][c];
          }
        }
      }
    }
    __syncthreads();                     // partials visible
    if (wh == 0){
      #pragma unroll
      for (int j = 0; j < 4; j++){
        if (j >= JN) break;
        #pragma unroll
        for (int c = 0; c < 4; c++){
          int o = wn * 32 + 8 * j + 2 * lc + (c & 1);
          if (o < 50){
            int rl = wm * 16 + lr + ((c >> 1) << 3);
            float m = fmaxf(mx[j][c], part[rl * 50 + o]);
            size_t base = (size_t)(b0 + rl) * 450 + (size_t)(o * 9 + s);
            out[base]                    = m;
            out[base + (size_t)NB * 450] = (m > THRESH) ? 1.0f : 0.0f;
          }
        }
      }
    }
    __syncthreads();                     // partials consumed; xbuf[cur] reloadable
    cur ^= 1;
  }
}

extern "C" void kernel_launch(void* const* d_in, const int* in_sizes, int n_in,
                              void* d_out, int out_size)
{
  const float* x = (const float*)d_in[0];
  const float* W = (const float*)d_in[1];
  if (n_in >= 2 && in_sizes[0] < in_sizes[1]) {
    x = (const float*)d_in[1];
    W = (const float*)d_in[0];
  }
  float* out = (float*)d_out;

  prep_x_kernel<<<(NB * 410 + 255) / 256, 256>>>(x);
  prep_w_kernel<<<54, 256>>>(W);

  cudaFuncSetAttribute(conv_main,
                       cudaFuncAttributeMaxDynamicSharedMemorySize, SMEM_BYTES);
  conv_main<<<NB / 32, NTHR, SMEM_BYTES>>>(out);
}

// round 13
// speedup vs baseline: 1.0521x; 1.0521x over previous
#include <cuda_runtime.h>
#include <cstdint>

// Conv_39333310497378 — fp16 mma.sync; smem-staged output (one coalesced
// flush kills the 36B-stride store amplification); x converted inline
// (LDG->cvt->STS), W pre-converted once by prep_w.
// pot(b,s,o) = max_{h<4} sum_{k<240} x[b*1640 + 160s + 40h + k] * W[s,o,k]
// out: pots [B,50,9] then spikes [B,50,9] (f32), index b*450 + o*9 + s.

#define NB      16384
#define XSLAB   1640
#define THRESH  6.2f
#define NTHR    256

#define XSTRW   180        // xbuf row stride (words); banks 20*lr+lc: full perm
#define WSTRW   124        // wbuf row stride (words); banks 28*lr+lc: full perm
#define WROWS   56
#define WSEC    (WROWS * WSTRW)              // 6944 words

__device__ uint32_t g_w16[9 * WSEC];         // 250 KB, zero-init (pad rows = 0)

// smem words: xbuf [0,5760) | wbuf [5760,12704) | stage [12704,27104)
#define XBUF_WORDS (32 * XSTRW)              // 5760
#define WB_OFF     XBUF_WORDS
#define STG_OFF    (WB_OFF + WSEC)           // 12704
#define STG_WORDS  (32 * 450)                // 14400
#define SMEM_BYTES ((STG_OFF + STG_WORDS) * 4)   // 108416 -> 2 CTAs/SM

__global__ void prep_w_kernel(const float* __restrict__ W)
{
  int i = blockIdx.x * blockDim.x + threadIdx.x;   // 8-float chunks
  if (i >= 9 * 50 * 30) return;
  int s = i / 1500, rem = i - s * 1500;
  int o = rem / 30,  q  = rem - o * 30;
  const float* src = W + ((size_t)(s * 50 + o) * 240 + 8 * q);
  float4 v0 = *reinterpret_cast<const float4*>(src);
  float4 v1 = *reinterpret_cast<const float4*>(src + 4);
  uint4 t;
  asm("cvt.rn.f16x2.f32 %0, %1, %2;" : "=r"(t.x) : "f"(v0.y), "f"(v0.x));
  asm("cvt.rn.f16x2.f32 %0, %1, %2;" : "=r"(t.y) : "f"(v0.w), "f"(v0.z));
  asm("cvt.rn.f16x2.f32 %0, %1, %2;" : "=r"(t.z) : "f"(v1.y), "f"(v1.x));
  asm("cvt.rn.f16x2.f32 %0, %1, %2;" : "=r"(t.w) : "f"(v1.w), "f"(v1.z));
  *reinterpret_cast<uint4*>(g_w16 + s * WSEC + o * WSTRW + 4 * q) = t;
}

__device__ __forceinline__ uint32_t s2u(const void* p){
  uint32_t a;
  asm("{.reg .u64 t; cvta.to.shared.u64 t, %1; cvt.u32.u64 %0, t;}" : "=r"(a) : "l"(p));
  return a;
}
__device__ __forceinline__ void cp16(uint32_t dst, const void* src){
  asm volatile("cp.async.cg.shared.global [%0], [%1], 16;" :: "r"(dst), "l"(src) : "memory");
}

// Warp computes 2 h-windows (h = 2*wh + hh) for JN n-frags; returns max over
// its two h per element.
template<int JN>
__device__ __forceinline__ void core(const uint32_t* __restrict__ xb,
                                     const uint32_t* __restrict__ wb,
                                     int wm, int wn, int wh, int lr, int lc,
                                     float (&mx)[4][4])
{
  float d[2][JN][4];
  #pragma unroll
  for (int hh = 0; hh < 2; hh++)
    #pragma unroll
    for (int j = 0; j < JN; j++)
      #pragma unroll
      for (int c = 0; c < 4; c++) d[hh][j][c] = 0.f;

  const int ar = (wm * 16 + lr) * XSTRW + lc + 40 * wh;
  const int wr = (wn * 32 + lr) * WSTRW + lc;

  #pragma unroll 5
  for (int ks = 0; ks < 15; ks++)
  {
    const int ko = 8 * ks;
    uint32_t b[JN][2];
    #pragma unroll
    for (int j = 0; j < JN; j++){
      b[j][0] = wb[wr + j * (8 * WSTRW) + ko];
      b[j][1] = wb[wr + j * (8 * WSTRW) + ko + 4];
    }
    uint32_t a[2][4];
    #pragma unroll
    for (int hh = 0; hh < 2; hh++){
      int wa = ar + 20 * hh + ko;
      a[hh][0] = xb[wa];
      a[hh][1] = xb[wa + 8 * XSTRW];
      a[hh][2] = xb[wa + 4];
      a[hh][3] = xb[wa + 8 * XSTRW + 4];
    }
    #pragma unroll
    for (int hh = 0; hh < 2; hh++)
      #pragma unroll
      for (int j = 0; j < JN; j++)
        asm("mma.sync.aligned.m16n8k16.row.col.f32.f16.f16.f32 "
            "{%0,%1,%2,%3},{%4,%5,%6,%7},{%8,%9},{%0,%1,%2,%3};"
            : "+f"(d[hh][j][0]), "+f"(d[hh][j][1]),
              "+f"(d[hh][j][2]), "+f"(d[hh][j][3])
            : "r"(a[hh][0]), "r"(a[hh][1]), "r"(a[hh][2]), "r"(a[hh][3]),
              "r"(b[j][0]), "r"(b[j][1]));
  }

  #pragma unroll
  for (int j = 0; j < JN; j++)
    #pragma unroll
    for (int c = 0; c < 4; c++)
      mx[j][c] = fmaxf(d[0][j][c], d[1][j][c]);
}

__global__ void __launch_bounds__(NTHR, 2)
conv_main(const float* __restrict__ x, float* __restrict__ out)
{
  extern __shared__ uint32_t sm[];
  uint32_t* xb  = sm;
  uint32_t* wb  = sm + WB_OFF;
  float*    stg = reinterpret_cast<float*>(sm + STG_OFF);  // [32][50][9]

  const uint32_t wsa = s2u(wb);

  const int tid  = threadIdx.x;
  const int warp = tid >> 5, lane = tid & 31;
  const int lr = lane >> 2, lc = lane & 3;
  const int wm = warp & 1, wn = (warp >> 1) & 1, wh = warp >> 2;
  const int b0 = blockIdx.x * 32;
  const int JN = (wn == 0) ? 4 : 3;

  // x(s): LDG.128 f32 -> fp16x2 -> STS.64 into xbuf (inline convert).
  auto load_x = [&](int s){
    #pragma unroll 3
    for (int i = tid; i < 2880; i += NTHR){       // 90 float4 x 32 rows
      int row = i / 90, c = i - row * 90;
      float4 v = *reinterpret_cast<const float4*>(
          x + (size_t)(b0 + row) * XSLAB + 160 * s + 4 * c);
      uint32_t w0, w1;
      asm("cvt.rn.f16x2.f32 %0, %1, %2;" : "=r"(w0) : "f"(v.y), "f"(v.x));
      asm("cvt.rn.f16x2.f32 %0, %1, %2;" : "=r"(w1) : "f"(v.w), "f"(v.z));
      *reinterpret_cast<uint2*>(xb + row * XSTRW + 2 * c) = make_uint2(w0, w1);
    }
  };
  auto load_w = [&](int s){
    const uint32_t* src = g_w16 + s * WSEC;
    #pragma unroll 2
    for (int i = tid; i < WSEC / 4; i += NTHR)    // 1736 16B chunks
      cp16(wsa + 16u * (uint32_t)i, src + 4 * i);
    asm volatile("cp.async.commit_group;" ::: "memory");
  };

  load_w(0);
  load_x(0);
  asm volatile("cp.async.wait_group 0;" ::: "memory");
  __syncthreads();

  for (int s = 0; s < 9; s++)
  {
    float mx[4][4];
    if (wn == 0) core<4>(xb, wb, wm, 0, wh, lr, lc, mx);
    else         core<3>(xb, wb, wm, 1, wh, lr, lc, mx);

    __syncthreads();                  // xbuf + wbuf fully consumed

    if (s < 8) load_w(s + 1);         // wbuf free -> prefetch W

    if (wh == 1){                     // publish h{2,3} partials into stage slot
      #pragma unroll
      for (int j = 0; j < 4; j++){
        if (j >= JN) break;
        #pragma unroll
        for (int c = 0; c < 4; c++){
          int o = wn * 32 + 8 * j + 2 * lc + (c & 1);
          if (o < 50){
            int rl = wm * 16 + lr + ((c >> 1) << 3);
            stg[rl * 450 + o * 9 + s] = mx[j][c];
          }
        }
      }
    }

    if (s < 8) load_x(s + 1);         // xbuf free; overlaps w cp.async
    asm volatile("cp.async.wait_group 0;" ::: "memory");
    __syncthreads();                  // partials + xbuf + wbuf visible

    if (wh == 0){                     // combine h{0,1} with partner, finalize
      #pragma unroll
      for (int j = 0; j < 4; j++){
        if (j >= JN) break;
        #pragma unroll
        for (int c = 0; c < 4; c++){
          int o = wn * 32 + 8 * j + 2 * lc + (c & 1);
          if (o < 50){
            int rl = wm * 16 + lr + ((c >> 1) << 3);
            int idx = rl * 450 + o * 9 + s;
            stg[idx] = fmaxf(mx[j][c], stg[idx]);
          }
        }
      }
    }
  }

  __syncthreads();                    // stage complete

  // ---- Flush: each (r,o) -> 9 contiguous pots + 9 contiguous spikes ----
  for (int i = tid; i < 1600; i += NTHR){
    int r = i / 50, o = i - r * 50;
    float p[9];
    #pragma unroll
    for (int q = 0; q < 9; q++) p[q] = stg[r * 450 + o * 9 + q];
    size_t base = (size_t)(b0 + r) * 450 + (size_t)(o * 9);
    #pragma unroll
    for (int q = 0; q < 9; q++) out[base + q] = p[q];
    size_t sb_ = base + (size_t)NB * 450;
    #pragma unroll
    for (int q = 0; q < 9; q++) out[sb_ + q] = (p[q] > THRESH) ? 1.0f : 0.0f;
  }
}

extern "C" void kernel_launch(void* const* d_in, const int* in_sizes, int n_in,
                              void* d_out, int out_size)
{
  const float* x = (const float*)d_in[0];
  const float* W = (const float*)d_in[1];
  if (n_in >= 2 && in_sizes[0] < in_sizes[1]) {
    x = (const float*)d_in[1];
    W = (const float*)d_in[0];
  }
  float* out = (float*)d_out;

  prep_w_kernel<<<54, 256>>>(W);

  cudaFuncSetAttribute(conv_main,
                       cudaFuncAttributeMaxDynamicSharedMemorySize, SMEM_BYTES);
  conv_main<<<NB / 32, NTHR, SMEM_BYTES>>>(x, out);
}

// round 15
// speedup vs baseline: 1.4479x; 1.3762x over previous
#include <cuda_runtime.h>
#include <cstdint>

// Conv_39333310497378 — fp16 mma.sync + ldmatrix; flat grid (one GEMM per
// CTA, no s-loop). W pre-converted to fp16 once (prep_w); x converted inline.
// pot(b,s,o) = max_{h<4} sum_{k<240} x[b*1640 + 160s + 40h + k] * W[s,o,k]
// out: pots [B,50,9] then spikes [B,50,9] (f32), index b*450 + o*9 + s.

#define NB      16384
#define XSLAB   1640
#define THRESH  6.2f
#define NTHR    128

#define XSTRW   180        // xbuf row stride (words); 180%32=20 -> LDSM conflict-free
#define WSTRW   124        // wbuf row stride (words); 124%32=28 -> conflict-free
#define WROWS   56
#define WSEC    (WROWS * WSTRW)              // 6944 words

__device__ uint32_t g_w16[9 * WSEC];         // 250 KB, zero-init (pad rows = 0)

#define XBUF_WORDS (32 * XSTRW)              // 5760
#define SMEM_BYTES ((XBUF_WORDS + WSEC) * 4) // 50816 -> 4 CTAs/SM

__global__ void prep_w_kernel(const float* __restrict__ W)
{
  int i = blockIdx.x * blockDim.x + threadIdx.x;   // 8-float chunks
  if (i >= 9 * 50 * 30) return;
  int s = i / 1500, rem = i - s * 1500;
  int o = rem / 30,  q  = rem - o * 30;
  const float* src = W + ((size_t)(s * 50 + o) * 240 + 8 * q);
  float4 v0 = *reinterpret_cast<const float4*>(src);
  float4 v1 = *reinterpret_cast<const float4*>(src + 4);
  uint4 t;
  asm("cvt.rn.f16x2.f32 %0, %1, %2;" : "=r"(t.x) : "f"(v0.y), "f"(v0.x));
  asm("cvt.rn.f16x2.f32 %0, %1, %2;" : "=r"(t.y) : "f"(v0.w), "f"(v0.z));
  asm("cvt.rn.f16x2.f32 %0, %1, %2;" : "=r"(t.z) : "f"(v1.y), "f"(v1.x));
  asm("cvt.rn.f16x2.f32 %0, %1, %2;" : "=r"(t.w) : "f"(v1.w), "f"(v1.z));
  *reinterpret_cast<uint4*>(g_w16 + s * WSEC + o * WSTRW + 4 * q) = t;
}

__device__ __forceinline__ uint32_t s2u(const void* p){
  uint32_t a;
  asm("{.reg .u64 t; cvta.to.shared.u64 t, %1; cvt.u32.u64 %0, t;}" : "=r"(a) : "l"(p));
  return a;
}
__device__ __forceinline__ void cp16(uint32_t dst, const void* src){
  asm volatile("cp.async.cg.shared.global [%0], [%1], 16;" :: "r"(dst), "l"(src) : "memory");
}
__device__ __forceinline__ void ldsm4(uint32_t* r, uint32_t a){
  asm volatile("ldmatrix.sync.aligned.m8n8.x4.shared.b16 {%0,%1,%2,%3}, [%4];"
               : "=r"(r[0]), "=r"(r[1]), "=r"(r[2]), "=r"(r[3]) : "r"(a));
}
__device__ __forceinline__ void ldsm2(uint32_t* r, uint32_t a){
  asm volatile("ldmatrix.sync.aligned.m8n8.x2.shared.b16 {%0,%1}, [%2];"
               : "=r"(r[0]), "=r"(r[1]) : "r"(a));
}

// Warp: m16 tile (wm), n-group (wn: JN frags), all 4 h-windows.
// LDSM lane setup (mi = lane>>3, r = lane&7):
//   A  x4: regs {rowlo/klo, rowhi/klo, rowlo/khi, rowhi/khi} -> rh=mi&1, kh=mi>>1
//   B  x4: regs {j0 klo, j0 khi, j1 klo, j1 khi}            -> j=j0+(mi>>1), kh=mi&1
template<int JN>
__device__ __forceinline__ void core(uint32_t aAddr, uint32_t bAddr0,
                                     uint32_t bAddr1, uint32_t bAddrX2,
                                     int wm, int wn, int lr, int lc,
                                     int b0, int s, float* __restrict__ out)
{
  float d[4][JN][4];
  #pragma unroll
  for (int h = 0; h < 4; h++)
    #pragma unroll
    for (int j = 0; j < JN; j++)
      #pragma unroll
      for (int c = 0; c < 4; c++) d[h][j][c] = 0.f;

  #pragma unroll 3
  for (int ks = 0; ks < 15; ks++)
  {
    const uint32_t kb = (uint32_t)(32 * ks);        // 8 words per k-step
    uint32_t a[4][4];
    #pragma unroll
    for (int h = 0; h < 4; h++)
      ldsm4(a[h], aAddr + 80u * h + kb);            // 20 words = 80 B per h
    uint32_t b[4][2];
    ldsm4(&b[0][0], bAddr0 + kb);                   // j0=0,1
    if (JN == 4) ldsm4(&b[2][0], bAddr1 + kb);      // j0=2,3
    else         ldsm2(&b[2][0], bAddrX2 + kb);     // j=2

    #pragma unroll
    for (int h = 0; h < 4; h++)
      #pragma unroll
      for (int j = 0; j < JN; j++)
        asm("mma.sync.aligned.m16n8k16.row.col.f32.f16.f16.f32 "
            "{%0,%1,%2,%3},{%4,%5,%6,%7},{%8,%9},{%0,%1,%2,%3};"
            : "+f"(d[h][j][0]), "+f"(d[h][j][1]),
              "+f"(d[h][j][2]), "+f"(d[h][j][3])
            : "r"(a[h][0]), "r"(a[h][1]), "r"(a[h][2]), "r"(a[h][3]),
              "r"(b[j][0]), "r"(b[j][1]));
  }

  #pragma unroll
  for (int j = 0; j < JN; j++)
    #pragma unroll
    for (int c = 0; c < 4; c++){
      int o = wn * 32 + 8 * j + 2 * lc + (c & 1);
      if (o < 50){
        float m = fmaxf(fmaxf(d[0][j][c], d[1][j][c]),
                        fmaxf(d[2][j][c], d[3][j][c]));
        int row = b0 + wm * 16 + lr + ((c >> 1) << 3);
        size_t base = (size_t)row * 450 + (size_t)(o * 9 + s);
        out[base]                    = m;
        out[base + (size_t)NB * 450] = (m > THRESH) ? 1.0f : 0.0f;
      }
    }
}

__global__ void __launch_bounds__(NTHR, 4)
conv_main(const float* __restrict__ x, float* __restrict__ out)
{
  extern __shared__ uint32_t sm[];
  uint32_t* xb = sm;                 // [32][XSTRW] fp16x2 words
  uint32_t* wb = sm + XBUF_WORDS;    // [56][WSTRW]

  const uint32_t xsa = s2u(xb);
  const uint32_t wsa = s2u(wb);

  const int tid  = threadIdx.x;
  const int warp = tid >> 5, lane = tid & 31;
  const int lr = lane >> 2, lc = lane & 3;
  const int wm = warp & 1,  wn = warp >> 1;
  const int s  = blockIdx.x;         // s fastest -> same-tile CTAs adjacent (L2)
  const int b0 = blockIdx.y * 32;

  // ---- W(s): cp.async from pre-converted fp16 scratch ----
  {
    const uint32_t* src = g_w16 + s * WSEC;
    #pragma unroll 2
    for (int i = tid; i < WSEC / 4; i += NTHR)     // 1736 16B chunks
      cp16(wsa + 16u * (uint32_t)i, src + 4 * i);
    asm volatile("cp.async.commit_group;" ::: "memory");
  }
  // ---- x window: LDG.128 f32 -> fp16x2 -> STS.64 ----
  {
    #pragma unroll 4
    for (int i = tid; i < 2880; i += NTHR){        // 90 float4 x 32 rows
      int row = i / 90, c = i - row * 90;
      float4 v = *reinterpret_cast<const float4*>(
          x + (size_t)(b0 + row) * XSLAB + 160 * s + 4 * c);
      uint32_t w0, w1;
      asm("cvt.rn.f16x2.f32 %0, %1, %2;" : "=r"(w0) : "f"(v.y), "f"(v.x));
      asm("cvt.rn.f16x2.f32 %0, %1, %2;" : "=r"(w1) : "f"(v.w), "f"(v.z));
      *reinterpret_cast<uint2*>(xb + row * XSTRW + 2 * c) = make_uint2(w0, w1);
    }
  }
  asm volatile("cp.async.wait_group 0;" ::: "memory");
  __syncthreads();

  // ---- LDSM lane addresses ----
  const int mi = lane >> 3, r = lane & 7;
  const uint32_t aAddr  = xsa +
      (uint32_t)(((wm * 16 + (mi & 1) * 8 + r) * XSTRW + (mi >> 1) * 4) * 4);
  const uint32_t bAddr0 = wsa +
      (uint32_t)(((wn * 32 + 8 * (mi >> 1) + r) * WSTRW + (mi & 1) * 4) * 4);
  const uint32_t bAddr1 = bAddr0 + (uint32_t)(16 * WSTRW * 4);
  const uint32_t bAddrX2 = wsa +
      (uint32_t)(((wn * 32 + 16 + r) * WSTRW + (mi & 1) * 4) * 4);

  if (wn == 0) core<4>(aAddr, bAddr0, bAddr1, bAddrX2, wm, 0, lr, lc, b0, s, out);
  else         core<3>(aAddr, bAddr0, bAddr1, bAddrX2, wm, 1, lr, lc, b0, s, out);
}

extern "C" void kernel_launch(void* const* d_in, const int* in_sizes, int n_in,
                              void* d_out, int out_size)
{
  const float* x = (const float*)d_in[0];
  const float* W = (const float*)d_in[1];
  if (n_in >= 2 && in_sizes[0] < in_sizes[1]) {
    x = (const float*)d_in[1];
    W = (const float*)d_in[0];
  }
  float* out = (float*)d_out;

  prep_w_kernel<<<54, 256>>>(W);

  cudaFuncSetAttribute(conv_main,
                       cudaFuncAttributeMaxDynamicSharedMemorySize, SMEM_BYTES);

  dim3 grid(9, NB / 32);             // 9 x 512 = 4608 one-shot CTAs
  conv_main<<<grid, NTHR, SMEM_BYTES>>>(x, out);
}